// round 12
// baseline (speedup 1.0000x reference)
#include <cuda_runtime.h>

#define NTRAJ  2048
#define TSTEPS 512
#define KDIM   (TSTEPS * 3)
#define NCH    (3 * NTRAJ)     // 6144 chains
#define NLANE  (NCH / 2)       // 3072 lanes, 2 chains each
#define PF     8
#define DT     0.00833333333333333f

// Per-(t, chain) partials (S, mah), chain = c*NTRAJ + traj. 25 MB.
__device__ float2 g_part[TSTEPS * NCH];

__device__ __forceinline__ float htanh(float x) {
    float y; asm("tanh.approx.f32 %0, %1;" : "=f"(y) : "f"(x)); return y;
}
// rcp.approx + 1 Newton step: <=1 ulp vs IEEE 1/x. Required: the reference's
// om = 1-K0 cancellation amplifies reciprocal error by P0/r (~4e4).
__device__ __forceinline__ float frcp_nr(float x) {
    float y; asm("rcp.approx.f32 %0, %1;" : "=f"(y) : "f"(x));
    float e = fmaf(-x, y, 1.0f);
    return fmaf(e, y, y);
}

// One scalar-observation 2x2 Kalman step — EXACT R6 arithmetic (rel 3.9e-7).
__device__ __forceinline__ void kstep(
    float& s0, float& s1, float& p00, float& p01, float& p11,
    float z, float c1, float c2, float c3, float c4,
    float q0, float q1, float r, float& S_out, float& M_out)
{
    float sp = fmaf(DT, s1, s0);
    float tv = htanh(100.0f * s1);
    float vp = fmaf(-c2, tv, c1 * s1);
    float a  = fmaf(c3, tv * tv, c4);

    float u   = fmaf(DT, p11, p01);
    float n00 = fmaf(DT, u, fmaf(DT, p01, p00)) + q0;
    float n01 = a * u;
    float n11 = fmaf(a * a, p11, q1);

    float S  = n00 + r;
    float is = frcp_nr(S);
    float yv = z - sp;
    float K0 = __fmul_rn(n00, is);
    float K1 = __fmul_rn(n01, is);
    s0 = fmaf(K0, yv, sp);
    s1 = fmaf(K1, yv, vp);
    float om = 1.0f - K0;
    p00 = om * n00;
    p01 = om * n01;
    p11 = fmaf(-K1, n01, n11);

    S_out = S;
    M_out = yv * (is * yv);
}

// 3072 lanes x 2 independent chains per lane (chainA = L, chainB = L + 3072).
// The two chains' instruction streams interleave so chain B fills chain A's
// dependency-latency gaps (no SHFL/MIO in the loop — that was R7's poison).
__global__ void __launch_bounds__(32, 1) ekf_k(
    const float* __restrict__ meas,
    const float* __restrict__ init_state,
    const float* __restrict__ dyna,
    const float* __restrict__ Q,
    const float* __restrict__ R,
    const float* __restrict__ P0)
{
    const int lane = threadIdx.x & 31;
    const int L    = blockIdx.x * 32 + lane;

    const int chA = L,            chB = L + NLANE;
    const int cA  = chA >> 11,    cB  = chB >> 11;
    const int trA = chA & (NTRAJ - 1), trB = chB & (NTRAJ - 1);

    const float fricA = (cA == 2) ? 0.0f : __ldg(dyna + 0);
    const float dampA = (cA == 2) ? 0.0f : __ldg(dyna + 1);
    const float fricB = (cB == 2) ? 0.0f : __ldg(dyna + 0);
    const float dampB = (cB == 2) ? 0.0f : __ldg(dyna + 1);

    const float c1A = 1.0f - DT * dampA, c2A = DT * fricA;
    const float c3A = 100.0f * c2A,      c4A = c1A - c3A;
    const float c1B = 1.0f - DT * dampB, c2B = DT * fricB;
    const float c3B = 100.0f * c2B,      c4B = c1B - c3B;

    const int pcA = (cA == 2) ? 4 : cA, vcA = (cA == 2) ? 5 : cA + 2;
    const int pcB = (cB == 2) ? 4 : cB, vcB = (cB == 2) ? 5 : cB + 2;

    const float q0A = __ldg(Q + pcA * 7), q1A = __ldg(Q + vcA * 7), rA = __ldg(R + cA * 4);
    const float q0B = __ldg(Q + pcB * 7), q1B = __ldg(Q + vcB * 7), rB = __ldg(R + cB * 4);

    float s0A = init_state[trA * 6 + pcA], s1A = init_state[trA * 6 + vcA];
    float s0B = init_state[trB * 6 + pcB], s1B = init_state[trB * 6 + vcB];

    float p00A = __ldg(P0 + pcA * 7), p01A = __ldg(P0 + pcA * 6 + vcA), p11A = __ldg(P0 + vcA * 7);
    float p00B = __ldg(P0 + pcB * 7), p01B = __ldg(P0 + pcB * 6 + vcB), p11B = __ldg(P0 + vcB * 7);

    const float* zA = meas + trA * KDIM + cA;   // z(t) at zA[3t]
    const float* zB = meas + trB * KDIM + cB;
    float2* ppA = g_part + chA;
    float2* ppB = g_part + chB;

    float zrA[PF], zrB[PF];
    #pragma unroll
    for (int i = 0; i < PF; ++i) { zrA[i] = zA[3 * i]; zrB[i] = zB[3 * i]; }
    const float* pzA = zA + 3 * PF;
    const float* pzB = zB + 3 * PF;

    // main loop: 504 steps with unconditional prefetch (max step loaded = 511)
    #pragma unroll 1
    for (int t = 0; t < TSTEPS - PF; t += PF) {
        #pragma unroll
        for (int u8 = 0; u8 < PF; ++u8) {
            float za = zrA[u8], zb = zrB[u8];
            zrA[u8] = pzA[3 * u8];
            zrB[u8] = pzB[3 * u8];
            float SA, MA, SB, MB;
            kstep(s0A, s1A, p00A, p01A, p11A, za,
                  c1A, c2A, c3A, c4A, q0A, q1A, rA, SA, MA);
            kstep(s0B, s1B, p00B, p01B, p11B, zb,
                  c1B, c2B, c3B, c4B, q0B, q1B, rB, SB, MB);
            ppA[u8 * NCH] = make_float2(SA, MA);
            ppB[u8 * NCH] = make_float2(SB, MB);
        }
        pzA += 3 * PF; pzB += 3 * PF;
        ppA += PF * NCH; ppB += PF * NCH;
    }
    // tail: last 8 steps, no prefetch
    #pragma unroll
    for (int u8 = 0; u8 < PF; ++u8) {
        float SA, MA, SB, MB;
        kstep(s0A, s1A, p00A, p01A, p11A, zrA[u8],
              c1A, c2A, c3A, c4A, q0A, q1A, rA, SA, MA);
        kstep(s0B, s1B, p00B, p01B, p11B, zrB[u8],
              c1B, c2B, c3B, c4B, q0B, q1B, rB, SB, MB);
        ppA[u8 * NCH] = make_float2(SA, MA);
        ppB[u8 * NCH] = make_float2(SB, MB);
    }
}

// loss[traj][t] = (Sx*Sy)*St + (mx+my)+mt, smem-transposed.
__global__ void combine_k(float* __restrict__ out) {
    __shared__ float tile[32][33];
    const int t0  = blockIdx.x * 32;
    const int tr0 = blockIdx.y * 32;
    const int tx = threadIdx.x, ty = threadIdx.y;

    const float2* base = g_part + (t0 + ty) * NCH + tr0 + tx;
    float2 px = base[0];
    float2 py = base[NTRAJ];
    float2 pt = base[2 * NTRAJ];
    tile[ty][tx] = fmaf(px.x * py.x, pt.x, (px.y + py.y) + pt.y);
    __syncthreads();
    out[(tr0 + ty) * TSTEPS + t0 + tx] = tile[tx][ty];
}

extern "C" void kernel_launch(void* const* d_in, const int* in_sizes, int n_in,
                              void* d_out, int out_size) {
    const float* meas = (const float*)d_in[0];
    const float* init = (const float*)d_in[1];
    const float* dyna = (const float*)d_in[2];
    const float* Q    = (const float*)d_in[3];
    const float* R    = (const float*)d_in[4];
    const float* P0   = (const float*)d_in[5];
    float* out = (float*)d_out;

    ekf_k<<<NLANE / 32, 32>>>(meas, init, dyna, Q, R, P0);
    dim3 cgrid(TSTEPS / 32, NTRAJ / 32);
    combine_k<<<cgrid, dim3(32, 32)>>>(out);
}

// round 13
// speedup vs baseline: 1.3550x; 1.3550x over previous
#include <cuda_runtime.h>

#define NTRAJ  2048
#define TSTEPS 512
#define KDIM   (TSTEPS * 3)
#define NCH    (3 * NTRAJ)     // 6144 independent 2x2 Kalman chains
#define PF     8
#define DT     0.00833333333333333f

// Paired partials: g_part4[(t>>1)*NCH + chain] = (S_t, M_t, S_{t+1}, M_{t+1}).
// chain = c*NTRAJ + traj. 25 MB.
__device__ float4 g_part4[(TSTEPS / 2) * NCH];

__device__ __forceinline__ float htanh(float x) {
    float y; asm("tanh.approx.f32 %0, %1;" : "=f"(y) : "f"(x)); return y;
}
// rcp.approx + 1 Newton step: <=1 ulp vs IEEE 1/x. Required: the reference's
// om = 1-K0 cancellation amplifies reciprocal error by P0/r (~4e4).
__device__ __forceinline__ float frcp_nr(float x) {
    float y; asm("rcp.approx.f32 %0, %1;" : "=f"(y) : "f"(x));
    float e = fmaf(-x, y, 1.0f);
    return fmaf(e, y, y);
}

// One scalar-observation 2x2 Kalman step — R6-exact arithmetic (rel 3.9e-7).
__device__ __forceinline__ void kstep(
    float& s0, float& s1, float& p00, float& p01, float& p11,
    float z, float c1, float c2, float c3, float c4,
    float q0, float q1, float r, float& S_out, float& M_out)
{
    float sp = fmaf(DT, s1, s0);
    float tv = htanh(100.0f * s1);
    float vp = fmaf(-c2, tv, c1 * s1);
    float a  = fmaf(c3, tv * tv, c4);

    float u   = fmaf(DT, p11, p01);
    float n00 = fmaf(DT, u, fmaf(DT, p01, p00)) + q0;
    float n01 = a * u;
    float n11 = fmaf(a * a, p11, q1);

    float S  = n00 + r;
    float is = frcp_nr(S);
    float yv = z - sp;
    float K0 = __fmul_rn(n00, is);
    float K1 = __fmul_rn(n01, is);
    s0 = fmaf(K0, yv, sp);
    s1 = fmaf(K1, yv, vp);
    float om = 1.0f - K0;
    p00 = om * n00;
    p01 = om * n01;
    p11 = fmaf(-K1, n01, n11);

    S_out = S;
    M_out = yv * (is * yv);
}

// 6144 chains, one per lane (192 warps, no per-lane ILP — proven optimal).
// z read directly from [traj][t][k] layout (12B/step stride -> ~90% L1 hits).
// Partials written as one STG.128 per 2 steps.
__global__ void __launch_bounds__(32, 1) ekf_k(
    const float* __restrict__ meas,
    const float* __restrict__ init_state,
    const float* __restrict__ dyna,
    const float* __restrict__ Q,
    const float* __restrict__ R,
    const float* __restrict__ P0)
{
    const int lane  = threadIdx.x & 31;
    const int chain = blockIdx.x * 32 + lane;
    const int c     = chain >> 11;          // 0,1,2
    const int traj  = chain & (NTRAJ - 1);

    const bool lin = (c == 2);
    const float fric = lin ? 0.0f : __ldg(dyna + 0);
    const float damp = lin ? 0.0f : __ldg(dyna + 1);

    const float c1 = 1.0f - DT * damp;
    const float c2 = DT * fric;
    const float c3 = 100.0f * c2;
    const float c4 = c1 - c3;

    const int pc = lin ? 4 : c;
    const int vc = lin ? 5 : c + 2;

    const float q0 = __ldg(Q + pc * 7);
    const float q1 = __ldg(Q + vc * 7);
    const float r  = __ldg(R + c * 4);

    float s0 = init_state[traj * 6 + pc];
    float s1 = init_state[traj * 6 + vc];

    float p00 = __ldg(P0 + pc * 7);
    float p01 = __ldg(P0 + pc * 6 + vc);
    float p11 = __ldg(P0 + vc * 7);

    const float* zb = meas + traj * KDIM + c;   // z(t) at zb[3*t]
    float4*      pp = g_part4 + chain;

    float zr[PF];
    #pragma unroll
    for (int i = 0; i < PF; ++i) zr[i] = zb[3 * i];

    const float* pz = zb + 3 * PF;

    float Sp, Mp;

    // main loop: 504 steps with unconditional prefetch (max step loaded = 511)
    #pragma unroll 1
    for (int t = 0; t < TSTEPS - PF; t += PF) {
        #pragma unroll
        for (int u8 = 0; u8 < PF; ++u8) {
            float z = zr[u8];
            zr[u8] = pz[3 * u8];
            float S, M;
            kstep(s0, s1, p00, p01, p11, z, c1, c2, c3, c4, q0, q1, r, S, M);
            if ((u8 & 1) == 0) { Sp = S; Mp = M; }
            else pp[(u8 >> 1) * NCH] = make_float4(Sp, Mp, S, M);
        }
        pz += 3 * PF;
        pp += (PF / 2) * NCH;
    }
    // tail: last 8 steps, no prefetch
    #pragma unroll
    for (int u8 = 0; u8 < PF; ++u8) {
        float S, M;
        kstep(s0, s1, p00, p01, p11, zr[u8], c1, c2, c3, c4, q0, q1, r, S, M);
        if ((u8 & 1) == 0) { Sp = S; Mp = M; }
        else pp[(u8 >> 1) * NCH] = make_float4(Sp, Mp, S, M);
    }
}

// loss[traj][t] = (Sx*Sy)*St + (mx+my)+mt from paired partials.
// Block (32,16): thread (tx,ty) loads one float4 per component (2 time steps),
// produces 2 losses into the smem transpose tile, then coalesced stores.
__global__ void combine_k(float* __restrict__ out) {
    __shared__ float tile[32][33];        // [t][traj]
    const int t0  = blockIdx.x * 32;
    const int tr0 = blockIdx.y * 32;
    const int tx = threadIdx.x, ty = threadIdx.y;   // ty in 0..15

    const float4* base = g_part4 + (t0 / 2 + ty) * NCH + tr0 + tx;
    float4 px = base[0];
    float4 py = base[NTRAJ];
    float4 pt = base[2 * NTRAJ];
    tile[2 * ty][tx]     = fmaf(px.x * py.x, pt.x, (px.y + py.y) + pt.y);
    tile[2 * ty + 1][tx] = fmaf(px.z * py.z, pt.z, (px.w + py.w) + pt.w);
    __syncthreads();
    out[(tr0 + ty) * TSTEPS + t0 + tx]      = tile[tx][ty];
    out[(tr0 + ty + 16) * TSTEPS + t0 + tx] = tile[tx][ty + 16];
}

extern "C" void kernel_launch(void* const* d_in, const int* in_sizes, int n_in,
                              void* d_out, int out_size) {
    const float* meas = (const float*)d_in[0];
    const float* init = (const float*)d_in[1];
    const float* dyna = (const float*)d_in[2];
    const float* Q    = (const float*)d_in[3];
    const float* R    = (const float*)d_in[4];
    const float* P0   = (const float*)d_in[5];
    float* out = (float*)d_out;

    ekf_k<<<NCH / 32, 32>>>(meas, init, dyna, Q, R, P0);
    dim3 cgrid(TSTEPS / 32, NTRAJ / 32);
    combine_k<<<cgrid, dim3(32, 16)>>>(out);
}